// round 7
// baseline (speedup 1.0000x reference)
#include <cuda_runtime.h>
#include <cstdint>

#define BB 64
#define TT 1024
#define II 256
#define HH 512
#define G4 2048
#define NCTA 128          // persistent CTAs, 1/SM (big smem) -> co-resident
#define NC 16             // gate columns per CTA (4 h-cols x 4 gates)
#define VT_S 516          // smem strides == 4 (mod 32) -> conflict-free fragments
#define HS_S 516
#define GS_S 18
#define REC_SMEM_FLOATS (NC*VT_S + 64*HS_S + 2*64*GS_S)
#define REC_SMEM_BYTES (REC_SMEM_FLOATS * 4)

// -------- global scratch (static device memory; no runtime allocation) -----
__device__ float g_xproj[(size_t)BB * TT * G4];   // [t*64+b][2048], bias folded
__device__ float g_hbuf[2][BB * HH];              // h ping-pong, tf32-pre-rounded
__device__ int   g_cnt;                            // monotonic arrival counter

// -------- helpers -----------------------------------------------------------
__device__ __forceinline__ float tf32r(float f) {
    unsigned u; asm("cvt.rna.tf32.f32 %0, %1;" : "=r"(u) : "f"(f));
    return __uint_as_float(u);
}
__device__ __forceinline__ unsigned fb(float f) { return __float_as_uint(f); }

__device__ __forceinline__ void mma_tf32(float* c,
    unsigned a0, unsigned a1, unsigned a2, unsigned a3, unsigned b0, unsigned b1) {
    asm volatile(
        "mma.sync.aligned.m16n8k8.row.col.f32.tf32.tf32.f32 "
        "{%0,%1,%2,%3},{%4,%5,%6,%7},{%8,%9},{%0,%1,%2,%3};"
        : "+f"(c[0]), "+f"(c[1]), "+f"(c[2]), "+f"(c[3])
        : "r"(a0), "r"(a1), "r"(a2), "r"(a3), "r"(b0), "r"(b1));
}
__device__ __forceinline__ int ld_acq(const int* p) {
    int v; asm volatile("ld.acquire.gpu.s32 %0, [%1];" : "=r"(v) : "l"(p) : "memory");
    return v;
}
__device__ __forceinline__ void red_rel_add(int* p, int v) {
    asm volatile("red.release.gpu.global.add.s32 [%0], %1;" :: "l"(p), "r"(v) : "memory");
}
__device__ __forceinline__ void cp_async16(uint32_t s, const void* g) {
    asm volatile("cp.async.cg.shared.global [%0], [%1], 16;" :: "r"(s), "l"(g));
}
__device__ __forceinline__ void cp_commit() {
    asm volatile("cp.async.commit_group;" ::: "memory");
}
template<int P> __device__ __forceinline__ void cp_wait() {
    asm volatile("cp.async.wait_group %0;" :: "n"(P) : "memory");
}
__device__ __forceinline__ float fsig(float x) {
    return 1.0f / (1.0f + __expf(-x));
}
__device__ __forceinline__ float ftanh(float x) {
    float e = __expf(-2.0f * fabsf(x));          // in (0,1], overflow-free
    float r = (1.0f - e) / (1.0f + e);
    return copysignf(r, x);
}

// -------- reset (state reinitialized on every graph replay) -----------------
__global__ void reset_kernel() {
    int tid = threadIdx.x + blockIdx.x * blockDim.x;
    for (int i = tid; i < BB * HH; i += blockDim.x * gridDim.x) g_hbuf[0][i] = 0.0f;
    if (tid == 0) g_cnt = 0;
}

// -------- phase 1: g_xproj[r][n] = x @ [U_i|U_f|U_h|U_o] + b ---------------
__global__ void __launch_bounds__(256) xproj_kernel(
    const float* __restrict__ x,
    const float* __restrict__ Ui, const float* __restrict__ Uf,
    const float* __restrict__ Uh, const float* __restrict__ Uo,
    const float* __restrict__ bi, const float* __restrict__ bf,
    const float* __restrict__ bh, const float* __restrict__ bo)
{
    __shared__ float As[128 * 36];
    __shared__ float Bs[32 * 72];
    __shared__ float bias_s[64];

    const int tid = threadIdx.x;
    const int n0 = blockIdx.x * 64;
    const int m0 = blockIdx.y * 128;
    const int q  = n0 >> 9;
    const int c0 = n0 & 511;

    const float* Uq = (q == 0) ? Ui : (q == 1) ? Uf : (q == 2) ? Uh : Uo;
    const float* bq = (q == 0) ? bi : (q == 1) ? bf : (q == 2) ? bh : bo;
    if (tid < 64) bias_s[tid] = bq[c0 + tid];

    const int w = tid >> 5, lane = tid & 31, g = lane >> 2, tig = lane & 3;
    const int warpM = w >> 1, warpN = w & 1;

    const int arow = tid >> 1, ahalf = tid & 1;
    const int r  = m0 + arow;
    const int bbi = r & 63, tti = r >> 6;
    const float* xrow = x + ((size_t)bbi * TT + tti) * II;
    const int brow = tid >> 3, bcol8 = (tid & 7) * 8;

    float acc[2][4][4] = {};

    for (int kc = 0; kc < 8; ++kc) {
        const int k0 = kc * 32;
        #pragma unroll
        for (int i = 0; i < 4; ++i) {
            float4 v = *(const float4*)(xrow + k0 + ahalf * 16 + i * 4);
            int off = arow * 36 + ahalf * 16 + i * 4;
            As[off+0] = tf32r(v.x); As[off+1] = tf32r(v.y);
            As[off+2] = tf32r(v.z); As[off+3] = tf32r(v.w);
        }
        #pragma unroll
        for (int i = 0; i < 2; ++i) {
            float4 v = *(const float4*)(Uq + (size_t)(k0 + brow) * HH + c0 + bcol8 + i * 4);
            int off = brow * 72 + bcol8 + i * 4;
            Bs[off+0] = tf32r(v.x); Bs[off+1] = tf32r(v.y);
            Bs[off+2] = tf32r(v.z); Bs[off+3] = tf32r(v.w);
        }
        __syncthreads();

        #pragma unroll
        for (int kk = 0; kk < 32; kk += 8) {
            unsigned a[2][4];
            #pragma unroll
            for (int i2 = 0; i2 < 2; ++i2) {
                int rb = warpM * 32 + i2 * 16;
                a[i2][0] = fb(As[(rb + g    ) * 36 + kk + tig]);
                a[i2][1] = fb(As[(rb + g + 8) * 36 + kk + tig]);
                a[i2][2] = fb(As[(rb + g    ) * 36 + kk + tig + 4]);
                a[i2][3] = fb(As[(rb + g + 8) * 36 + kk + tig + 4]);
            }
            #pragma unroll
            for (int nt = 0; nt < 4; ++nt) {
                int nn = warpN * 32 + nt * 8 + g;
                unsigned b0 = fb(Bs[(kk + tig    ) * 72 + nn]);
                unsigned b1 = fb(Bs[(kk + tig + 4) * 72 + nn]);
                mma_tf32(acc[0][nt], a[0][0], a[0][1], a[0][2], a[0][3], b0, b1);
                mma_tf32(acc[1][nt], a[1][0], a[1][1], a[1][2], a[1][3], b0, b1);
            }
        }
        __syncthreads();
    }

    #pragma unroll
    for (int i2 = 0; i2 < 2; ++i2) {
        #pragma unroll
        for (int nt = 0; nt < 4; ++nt) {
            int coll = warpN * 32 + nt * 8 + 2 * tig;
            float b0v = bias_s[coll], b1v = bias_s[coll + 1];
            int row0 = m0 + warpM * 32 + i2 * 16 + g;
            *(float2*)&g_xproj[(size_t)row0 * G4 + n0 + coll] =
                make_float2(acc[i2][nt][0] + b0v, acc[i2][nt][1] + b1v);
            *(float2*)&g_xproj[(size_t)(row0 + 8) * G4 + n0 + coll] =
                make_float2(acc[i2][nt][2] + b0v, acc[i2][nt][3] + b1v);
        }
    }
}

// -------- phase 2: persistent recurrence -------------------------------------
// Pipelined: h staged in 4 K-chunks of 128 (cp.async groups), MMA on chunk c
// overlaps the in-flight copies of chunks c+1..3.
// Warps: 8 = 4 M-warps x 2 K-subs. Warp tile per chunk: 16M x 16N x 64K.
__global__ void __launch_bounds__(256, 1) lstm_rec_kernel(
    const float* __restrict__ Vi, const float* __restrict__ Vf,
    const float* __restrict__ Vh, const float* __restrict__ Vo)
{
    extern __shared__ float sm[];
    float* Vt = sm;                   // [16][516] tf32 V slice, [n][k]
    float* hs = Vt + NC * VT_S;       // [64][516] staged h (already tf32)
    float* gs = hs + 64 * HS_S;       // [2][64][18] partial-gate exchange

    const int tid = threadIdx.x, cta = blockIdx.x;
    const int hc0 = cta * 4;
    const int w = tid >> 5, lane = tid & 31, g = lane >> 2, tig = lane & 3;
    const int mw = w & 3, ks = w >> 2;

    // load this CTA's V slice once (tf32-rounded), layout [n][k]
    {
        const float* Vq[4] = { Vi, Vf, Vh, Vo };
        for (int idx = tid; idx < NC * HH; idx += 256) {
            int n = idx >> 9, k = idx & 511;
            Vt[n * VT_S + k] = tf32r(Vq[n >> 2][(size_t)k * HH + hc0 + (n & 3)]);
        }
    }
    __syncthreads();

    const int sb = tid >> 2, shc = tid & 3;            // this thread's (batch,hcol)
    const int srow = tid >> 2, sseg = tid & 3;         // staging map
    const uint32_t hs_u32 = (uint32_t)__cvta_generic_to_shared(hs);
    float c_state = 0.0f;

    const float* Abase = hs + (mw * 16) * HS_S + ks * 64;
    const float* Bbase = Vt + ks * 64;
    float* gsp = gs + ks * (64 * GS_S);

    for (int t = 0; t < TT; ++t) {
        // prefetch xproj (independent of h -> in flight during the spin)
        float xp[4];
        {
            const float* xb = g_xproj + ((size_t)t * BB + sb) * G4 + hc0 + shc;
            #pragma unroll
            for (int q2 = 0; q2 < 4; ++q2) xp[q2] = __ldg(xb + q2 * HH);
        }

        // wait for all CTAs to have published h_t
        if (t > 0 && tid == 0) {
            const int want = NCTA * t;
            while (ld_acq(&g_cnt) < want) { }
        }
        __syncthreads();

        // issue all 4 h chunks (one commit group each)
        {
            const float* hb = g_hbuf[t & 1] + srow * HH + sseg * 32;
            const uint32_t hd = hs_u32 + (uint32_t)(srow * HS_S + sseg * 32) * 4u;
            #pragma unroll
            for (int c = 0; c < 4; ++c) {
                #pragma unroll
                for (int i = 0; i < 8; ++i)
                    cp_async16(hd + (uint32_t)(c * 128 + i * 4) * 4u,
                               hb + c * 128 + i * 4);
                cp_commit();
            }
        }

        // MMA pipelined over chunks; accumulate across all 4 chunks
        float acc[2][4] = {};
        #pragma unroll
        for (int c = 0; c < 4; ++c) {
            if      (c == 0) cp_wait<3>();
            else if (c == 1) cp_wait<2>();
            else if (c == 2) cp_wait<1>();
            else             cp_wait<0>();
            __syncthreads();

            const float* Ab = Abase + c * 128;
            const float* Bb = Bbase + c * 128;
            #pragma unroll
            for (int kk = 0; kk < 64; kk += 8) {
                unsigned a0 = fb(Ab[(g    ) * HS_S + kk + tig]);
                unsigned a1 = fb(Ab[(g + 8) * HS_S + kk + tig]);
                unsigned a2 = fb(Ab[(g    ) * HS_S + kk + tig + 4]);
                unsigned a3 = fb(Ab[(g + 8) * HS_S + kk + tig + 4]);
                #pragma unroll
                for (int nt = 0; nt < 2; ++nt) {
                    unsigned b0 = fb(Bb[(nt * 8 + g) * VT_S + kk + tig]);
                    unsigned b1 = fb(Bb[(nt * 8 + g) * VT_S + kk + tig + 4]);
                    mma_tf32(acc[nt], a0, a1, a2, a3, b0, b1);
                }
            }
        }

        // write partial gates to exchange
        #pragma unroll
        for (int nt = 0; nt < 2; ++nt) {
            int col = nt * 8 + 2 * tig;
            *(float2*)&gsp[(mw * 16 + g    ) * GS_S + col] =
                make_float2(acc[nt][0], acc[nt][1]);
            *(float2*)&gsp[(mw * 16 + g + 8) * GS_S + col] =
                make_float2(acc[nt][2], acc[nt][3]);
        }
        __syncthreads();

        // elementwise gate update; c in register; h written tf32-pre-rounded
        {
            const float* g0 = gs + sb * GS_S + shc;
            const float* g1 = g0 + 64 * GS_S;
            float gi = g0[0]  + g1[0]  + xp[0];
            float gf = g0[4]  + g1[4]  + xp[1];
            float gg = g0[8]  + g1[8]  + xp[2];
            float go = g0[12] + g1[12] + xp[3];
            float it = fsig(gi), ft = fsig(gf), ot = fsig(go);
            float gt = ftanh(gg);
            c_state = ft * c_state + it * gt;
            g_hbuf[(t + 1) & 1][sb * HH + hc0 + shc] = tf32r(ot * ftanh(c_state));
        }
        __syncthreads();
        if (tid == 0) red_rel_add(&g_cnt, 1);
    }
}

// -------- phase 3: out[b] = h_last . fc_w + fc_b ----------------------------
__global__ void fc_kernel(const float* __restrict__ fc_w,
                          const float* __restrict__ fc_b, float* out) {
    int b = blockIdx.x, tid = threadIdx.x;
    const float* h = g_hbuf[0] + b * HH;   // h_1024 lives in buf[(1023+1)&1] = buf[0]
    float s = 0.0f;
    for (int k = tid; k < HH; k += 128) s += h[k] * fc_w[k];
    #pragma unroll
    for (int o = 16; o; o >>= 1) s += __shfl_down_sync(0xFFFFFFFFu, s, o);
    __shared__ float ws[4];
    if ((tid & 31) == 0) ws[tid >> 5] = s;
    __syncthreads();
    if (tid == 0) out[b] = ws[0] + ws[1] + ws[2] + ws[3] + fc_b[0];
}

// -------- launch -------------------------------------------------------------
extern "C" void kernel_launch(void* const* d_in, const int* in_sizes, int n_in,
                              void* d_out, int out_size) {
    const float* x   = (const float*)d_in[0];
    const float* Ui  = (const float*)d_in[1];
    const float* Vi  = (const float*)d_in[2];
    const float* bi  = (const float*)d_in[3];
    const float* Uf  = (const float*)d_in[4];
    const float* Vf  = (const float*)d_in[5];
    const float* bf  = (const float*)d_in[6];
    const float* Uh  = (const float*)d_in[7];
    const float* Vh  = (const float*)d_in[8];
    const float* bh  = (const float*)d_in[9];
    const float* Uo  = (const float*)d_in[10];
    const float* Vo  = (const float*)d_in[11];
    const float* bo  = (const float*)d_in[12];
    const float* fcw = (const float*)d_in[13];
    const float* fcb = (const float*)d_in[14];
    float* out = (float*)d_out;

    cudaFuncSetAttribute(lstm_rec_kernel,
                         cudaFuncAttributeMaxDynamicSharedMemorySize, REC_SMEM_BYTES);

    reset_kernel<<<64, 256>>>();
    dim3 gx(G4 / 64, (BB * TT) / 128);
    xproj_kernel<<<gx, 256>>>(x, Ui, Uf, Uh, Uo, bi, bf, bh, bo);
    lstm_rec_kernel<<<NCTA, 256, REC_SMEM_BYTES>>>(Vi, Vf, Vh, Vo);
    fc_kernel<<<BB, 128>>>(fcw, fcb, out);
}

// round 8
// speedup vs baseline: 1.4918x; 1.4918x over previous
#include <cuda_runtime.h>
#include <cuda_fp16.h>
#include <cstdint>

#define BB 64
#define TT 1024
#define II 256
#define HH 512
#define G4 2048
#define NCTA 128          // persistent CTAs, 1/SM -> co-resident
#define NC 16             // gate columns per CTA (4 h-cols x 4 gates)
#define VT2 520           // V smem stride in halves (word stride 260 == 4 mod 32)
#define HS2 520           // h smem stride in halves
#define GS_S 18
#define REC_SMEM_BYTES (NC*VT2*2 + 64*HS2*2 + 2*64*GS_S*4)

// -------- global scratch (static device memory; no runtime allocation) -----
__device__ float  g_xproj[(size_t)BB * TT * G4];  // [t*64+b][2048], bias folded
__device__ __half g_hbuf[2][BB * HH];             // h ping-pong, fp16
__device__ int    g_cnt;                          // monotonic arrival counter

// -------- helpers -----------------------------------------------------------
__device__ __forceinline__ float tf32r(float f) {
    unsigned u; asm("cvt.rna.tf32.f32 %0, %1;" : "=r"(u) : "f"(f));
    return __uint_as_float(u);
}
__device__ __forceinline__ unsigned fb(float f) { return __float_as_uint(f); }

__device__ __forceinline__ void mma_tf32(float* c,
    unsigned a0, unsigned a1, unsigned a2, unsigned a3, unsigned b0, unsigned b1) {
    asm volatile(
        "mma.sync.aligned.m16n8k8.row.col.f32.tf32.tf32.f32 "
        "{%0,%1,%2,%3},{%4,%5,%6,%7},{%8,%9},{%0,%1,%2,%3};"
        : "+f"(c[0]), "+f"(c[1]), "+f"(c[2]), "+f"(c[3])
        : "r"(a0), "r"(a1), "r"(a2), "r"(a3), "r"(b0), "r"(b1));
}
__device__ __forceinline__ void mma_f16(float* c,
    unsigned a0, unsigned a1, unsigned a2, unsigned a3, unsigned b0, unsigned b1) {
    asm volatile(
        "mma.sync.aligned.m16n8k16.row.col.f32.f16.f16.f32 "
        "{%0,%1,%2,%3},{%4,%5,%6,%7},{%8,%9},{%0,%1,%2,%3};"
        : "+f"(c[0]), "+f"(c[1]), "+f"(c[2]), "+f"(c[3])
        : "r"(a0), "r"(a1), "r"(a2), "r"(a3), "r"(b0), "r"(b1));
}
__device__ __forceinline__ int ld_acq(const int* p) {
    int v; asm volatile("ld.acquire.gpu.s32 %0, [%1];" : "=r"(v) : "l"(p) : "memory");
    return v;
}
__device__ __forceinline__ void red_rel_add(int* p, int v) {
    asm volatile("red.release.gpu.global.add.s32 [%0], %1;" :: "l"(p), "r"(v) : "memory");
}
__device__ __forceinline__ void cp_async16(uint32_t s, const void* g) {
    asm volatile("cp.async.cg.shared.global [%0], [%1], 16;" :: "r"(s), "l"(g));
}
__device__ __forceinline__ void cp_async_wait_all() {
    asm volatile("cp.async.commit_group;\n\tcp.async.wait_group 0;" ::: "memory");
}
__device__ __forceinline__ float fsig(float x) {
    return 1.0f / (1.0f + __expf(-x));
}
__device__ __forceinline__ float ftanh(float x) {
    float e = __expf(-2.0f * fabsf(x));          // in (0,1], overflow-free
    float r = (1.0f - e) / (1.0f + e);
    return copysignf(r, x);
}

// -------- reset (state reinitialized on every graph replay) -----------------
__global__ void reset_kernel() {
    int tid = threadIdx.x + blockIdx.x * blockDim.x;
    for (int i = tid; i < BB * HH; i += blockDim.x * gridDim.x)
        g_hbuf[0][i] = __float2half(0.0f);
    if (tid == 0) g_cnt = 0;
}

// -------- phase 1: g_xproj[r][n] = x @ [U_i|U_f|U_h|U_o] + b ---------------
__global__ void __launch_bounds__(256) xproj_kernel(
    const float* __restrict__ x,
    const float* __restrict__ Ui, const float* __restrict__ Uf,
    const float* __restrict__ Uh, const float* __restrict__ Uo,
    const float* __restrict__ bi, const float* __restrict__ bf,
    const float* __restrict__ bh, const float* __restrict__ bo)
{
    __shared__ float As[128 * 36];
    __shared__ float Bs[32 * 72];
    __shared__ float bias_s[64];

    const int tid = threadIdx.x;
    const int n0 = blockIdx.x * 64;
    const int m0 = blockIdx.y * 128;
    const int q  = n0 >> 9;
    const int c0 = n0 & 511;

    const float* Uq = (q == 0) ? Ui : (q == 1) ? Uf : (q == 2) ? Uh : Uo;
    const float* bq = (q == 0) ? bi : (q == 1) ? bf : (q == 2) ? bh : bo;
    if (tid < 64) bias_s[tid] = bq[c0 + tid];

    const int w = tid >> 5, lane = tid & 31, g = lane >> 2, tig = lane & 3;
    const int warpM = w >> 1, warpN = w & 1;

    const int arow = tid >> 1, ahalf = tid & 1;
    const int r  = m0 + arow;
    const int bbi = r & 63, tti = r >> 6;
    const float* xrow = x + ((size_t)bbi * TT + tti) * II;
    const int brow = tid >> 3, bcol8 = (tid & 7) * 8;

    float acc[2][4][4] = {};

    for (int kc = 0; kc < 8; ++kc) {
        const int k0 = kc * 32;
        #pragma unroll
        for (int i = 0; i < 4; ++i) {
            float4 v = *(const float4*)(xrow + k0 + ahalf * 16 + i * 4);
            int off = arow * 36 + ahalf * 16 + i * 4;
            As[off+0] = tf32r(v.x); As[off+1] = tf32r(v.y);
            As[off+2] = tf32r(v.z); As[off+3] = tf32r(v.w);
        }
        #pragma unroll
        for (int i = 0; i < 2; ++i) {
            float4 v = *(const float4*)(Uq + (size_t)(k0 + brow) * HH + c0 + bcol8 + i * 4);
            int off = brow * 72 + bcol8 + i * 4;
            Bs[off+0] = tf32r(v.x); Bs[off+1] = tf32r(v.y);
            Bs[off+2] = tf32r(v.z); Bs[off+3] = tf32r(v.w);
        }
        __syncthreads();

        #pragma unroll
        for (int kk = 0; kk < 32; kk += 8) {
            unsigned a[2][4];
            #pragma unroll
            for (int i2 = 0; i2 < 2; ++i2) {
                int rb = warpM * 32 + i2 * 16;
                a[i2][0] = fb(As[(rb + g    ) * 36 + kk + tig]);
                a[i2][1] = fb(As[(rb + g + 8) * 36 + kk + tig]);
                a[i2][2] = fb(As[(rb + g    ) * 36 + kk + tig + 4]);
                a[i2][3] = fb(As[(rb + g + 8) * 36 + kk + tig + 4]);
            }
            #pragma unroll
            for (int nt = 0; nt < 4; ++nt) {
                int nn = warpN * 32 + nt * 8 + g;
                unsigned b0 = fb(Bs[(kk + tig    ) * 72 + nn]);
                unsigned b1 = fb(Bs[(kk + tig + 4) * 72 + nn]);
                mma_tf32(acc[0][nt], a[0][0], a[0][1], a[0][2], a[0][3], b0, b1);
                mma_tf32(acc[1][nt], a[1][0], a[1][1], a[1][2], a[1][3], b0, b1);
            }
        }
        __syncthreads();
    }

    #pragma unroll
    for (int i2 = 0; i2 < 2; ++i2) {
        #pragma unroll
        for (int nt = 0; nt < 4; ++nt) {
            int coll = warpN * 32 + nt * 8 + 2 * tig;
            float b0v = bias_s[coll], b1v = bias_s[coll + 1];
            int row0 = m0 + warpM * 32 + i2 * 16 + g;
            *(float2*)&g_xproj[(size_t)row0 * G4 + n0 + coll] =
                make_float2(acc[i2][nt][0] + b0v, acc[i2][nt][1] + b1v);
            *(float2*)&g_xproj[(size_t)(row0 + 8) * G4 + n0 + coll] =
                make_float2(acc[i2][nt][2] + b0v, acc[i2][nt][3] + b1v);
        }
    }
}

// -------- phase 2: persistent recurrence (fp16 h/V, fp32 accum) -------------
// 8 warps = 4 M-warps x 2 K-halves. Warp tile 16M x 16N x 256K, mma m16n8k16.
__global__ void __launch_bounds__(256, 1) lstm_rec_kernel(
    const float* __restrict__ Vi, const float* __restrict__ Vf,
    const float* __restrict__ Vh, const float* __restrict__ Vo)
{
    extern __shared__ char smc[];
    __half* Vt = (__half*)smc;                          // [16][520] fp16 V, [n][k]
    __half* hs = (__half*)(smc + NC * VT2 * 2);         // [64][520] staged h fp16
    float*  gs = (float*)(smc + NC * VT2 * 2 + 64 * HS2 * 2);  // [2][64][18]

    const int tid = threadIdx.x, cta = blockIdx.x;
    const int hc0 = cta * 4;
    const int w = tid >> 5, lane = tid & 31, g = lane >> 2, tig = lane & 3;
    const int mw = w & 3, ks = w >> 2;

    // load this CTA's V slice once (fp16), layout [n][k]
    {
        const float* Vq[4] = { Vi, Vf, Vh, Vo };
        for (int idx = tid; idx < NC * HH; idx += 256) {
            int n = idx >> 9, k = idx & 511;
            Vt[n * VT2 + k] = __float2half_rn(Vq[n >> 2][(size_t)k * HH + hc0 + (n & 3)]);
        }
    }
    __syncthreads();

    const int sb = tid >> 2, shc = tid & 3;        // this thread's (batch,hcol)
    const int srow = tid >> 2, sseg = tid & 3;     // staging map: 128 halves each
    const uint32_t hs_u32 = (uint32_t)__cvta_generic_to_shared(hs);
    float c_state = 0.0f;

    const unsigned* Aw = (const unsigned*)hs + (mw * 16) * (HS2 / 2) + ks * 128;
    const unsigned* Bw = (const unsigned*)Vt + ks * 128;
    float* gsp = gs + ks * (64 * GS_S);

    for (int t = 0; t < TT; ++t) {
        // prefetch xproj (independent of h -> in flight during the spin)
        float xp[4];
        {
            const float* xb = g_xproj + ((size_t)t * BB + sb) * G4 + hc0 + shc;
            #pragma unroll
            for (int q2 = 0; q2 < 4; ++q2) xp[q2] = __ldg(xb + q2 * HH);
        }

        // wait for all CTAs to have published h_t
        if (t > 0 && tid == 0) {
            const int want = NCTA * t;
            while (ld_acq(&g_cnt) < want) { }
        }
        __syncthreads();

        // stage h_t (fp16) via cp.async: 16x16B per thread, coalesced
        {
            const char* hb = (const char*)(g_hbuf[t & 1] + srow * HH) + sseg * 256;
            const uint32_t hd = hs_u32 + (uint32_t)(srow * HS2 * 2 + sseg * 256);
            #pragma unroll
            for (int i = 0; i < 16; ++i)
                cp_async16(hd + (uint32_t)(i * 16), hb + i * 16);
            cp_async_wait_all();
        }
        __syncthreads();

        // gates_hV partials: warp (mw,ks), 16M x 16N x 256K via m16n8k16
        {
            float acc[2][2][4] = {};   // [nt][parity][4]
            #pragma unroll
            for (int it = 0; it < 16; ++it) {
                const int kw = it * 8;           // 16 halves = 8 words
                const int par = it & 1;
                unsigned a0 = Aw[(g    ) * (HS2/2) + kw + tig];
                unsigned a1 = Aw[(g + 8) * (HS2/2) + kw + tig];
                unsigned a2 = Aw[(g    ) * (HS2/2) + kw + 4 + tig];
                unsigned a3 = Aw[(g + 8) * (HS2/2) + kw + 4 + tig];
                #pragma unroll
                for (int nt = 0; nt < 2; ++nt) {
                    unsigned b0 = Bw[(nt * 8 + g) * (VT2/2) + kw + tig];
                    unsigned b1 = Bw[(nt * 8 + g) * (VT2/2) + kw + 4 + tig];
                    mma_f16(acc[nt][par], a0, a1, a2, a3, b0, b1);
                }
            }
            #pragma unroll
            for (int nt = 0; nt < 2; ++nt) {
                int col = nt * 8 + 2 * tig;
                *(float2*)&gsp[(mw * 16 + g    ) * GS_S + col] =
                    make_float2(acc[nt][0][0] + acc[nt][1][0],
                                acc[nt][0][1] + acc[nt][1][1]);
                *(float2*)&gsp[(mw * 16 + g + 8) * GS_S + col] =
                    make_float2(acc[nt][0][2] + acc[nt][1][2],
                                acc[nt][0][3] + acc[nt][1][3]);
            }
        }
        __syncthreads();

        // elementwise gate update; c in register; h stored fp16
        {
            const float* g0 = gs + sb * GS_S + shc;
            const float* g1 = g0 + 64 * GS_S;
            float gi = g0[0]  + g1[0]  + xp[0];
            float gf = g0[4]  + g1[4]  + xp[1];
            float gg = g0[8]  + g1[8]  + xp[2];
            float go = g0[12] + g1[12] + xp[3];
            float it = fsig(gi), ft = fsig(gf), ot = fsig(go);
            float gt = ftanh(gg);
            c_state = ft * c_state + it * gt;
            g_hbuf[(t + 1) & 1][sb * HH + hc0 + shc] =
                __float2half_rn(ot * ftanh(c_state));
        }
        __syncthreads();
        if (tid == 0) red_rel_add(&g_cnt, 1);
    }
}

// -------- phase 3: out[b] = h_last . fc_w + fc_b ----------------------------
__global__ void fc_kernel(const float* __restrict__ fc_w,
                          const float* __restrict__ fc_b, float* out) {
    int b = blockIdx.x, tid = threadIdx.x;
    const __half* h = g_hbuf[0] + b * HH;  // h_1024 in buf[(1023+1)&1] = buf[0]
    float s = 0.0f;
    for (int k = tid; k < HH; k += 128) s += __half2float(h[k]) * fc_w[k];
    #pragma unroll
    for (int o = 16; o; o >>= 1) s += __shfl_down_sync(0xFFFFFFFFu, s, o);
    __shared__ float ws[4];
    if ((tid & 31) == 0) ws[tid >> 5] = s;
    __syncthreads();
    if (tid == 0) out[b] = ws[0] + ws[1] + ws[2] + ws[3] + fc_b[0];
}

// -------- launch -------------------------------------------------------------
extern "C" void kernel_launch(void* const* d_in, const int* in_sizes, int n_in,
                              void* d_out, int out_size) {
    const float* x   = (const float*)d_in[0];
    const float* Ui  = (const float*)d_in[1];
    const float* Vi  = (const float*)d_in[2];
    const float* bi  = (const float*)d_in[3];
    const float* Uf  = (const float*)d_in[4];
    const float* Vf  = (const float*)d_in[5];
    const float* bf  = (const float*)d_in[6];
    const float* Uh  = (const float*)d_in[7];
    const float* Vh  = (const float*)d_in[8];
    const float* bh  = (const float*)d_in[9];
    const float* Uo  = (const float*)d_in[10];
    const float* Vo  = (const float*)d_in[11];
    const float* bo  = (const float*)d_in[12];
    const float* fcw = (const float*)d_in[13];
    const float* fcb = (const float*)d_in[14];
    float* out = (float*)d_out;

    cudaFuncSetAttribute(lstm_rec_kernel,
                         cudaFuncAttributeMaxDynamicSharedMemorySize, REC_SMEM_BYTES);

    reset_kernel<<<64, 256>>>();
    dim3 gx(G4 / 64, (BB * TT) / 128);
    xproj_kernel<<<gx, 256>>>(x, Ui, Uf, Uh, Uo, bi, bf, bh, bo);
    lstm_rec_kernel<<<NCTA, 256, REC_SMEM_BYTES>>>(Vi, Vf, Vh, Vo);
    fc_kernel<<<BB, 128>>>(fcw, fcb, out);
}